// round 1
// baseline (speedup 1.0000x reference)
#include <cuda_runtime.h>
#include <cstdint>
#include <cstddef>

#define BB 8
#define CC 256
#define NNDIM 1024
#define KDIM 16
#define CQ 64

// ---------------- scratch (device globals; no allocation allowed) ----------------
__device__ float g_wcat[384 * 256];                         // concat q/k/v weights
__device__ float g_xT[(size_t)BB * KDIM * CC * NNDIM];      // [b][k][c][n]  134MB
__device__ float g_xq[(size_t)BB * KDIM * CQ * NNDIM];      // [b][k][cq][n] 33.5MB
__device__ float g_xk[(size_t)BB * KDIM * CQ * NNDIM];      // [b][k][cq][n]
__device__ float g_xv[(size_t)BB * KDIM * CC * NNDIM];      // [b][k][c][n]  134MB
__device__ float g_S [(size_t)BB * KDIM * NNDIM * NNDIM];   // softmax probs  536MB
__device__ float g_d [(size_t)BB * KDIM * CC * NNDIM];      // x - x_r, [b][k][c][n]
__device__ float g_t [(size_t)BB * CC * KDIM * NNDIM];      // t proj, [b][c][k][n]
__device__ float g_a [CC];                                  // BN scale  (rstd*gamma)
__device__ float g_b2[CC];                                  // BN offset (beta - mean*a)

// ---------------- kernel 0: concat weights ----------------
__global__ void k_concat(const float* __restrict__ q_w, const float* __restrict__ k_w,
                         const float* __restrict__ v_w) {
    int i = blockIdx.x * 256 + threadIdx.x;
    if (i >= 384 * 256) return;
    int o = i >> 8;
    float v;
    if (o < 64)        v = q_w[i];
    else if (o < 128)  v = k_w[i - 64 * 256];
    else               v = v_w[i - 128 * 256];
    g_wcat[i] = v;
}

// ---------------- kernel 1: transpose x [b,c,n,k] -> xT [b,k,c,n] ----------------
__global__ void k_transpose_x(const float* __restrict__ x) {
    __shared__ float ts[16][68];
    int bc = blockIdx.x;             // b*256 + c
    int b = bc >> 8, c = bc & 255;
    int t = threadIdx.x;
    int nn = t >> 2, kg = (t & 3) << 2;       // load mapping: (n, k-group of 4)
    int kk = t >> 4, n4 = (t & 15) << 2;      // store mapping: (k, n-group of 4)
    for (int n0 = 0; n0 < NNDIM; n0 += 64) {
        float4 v = *(const float4*)&x[(((size_t)bc * NNDIM) + n0 + nn) * KDIM + kg];
        ts[kg + 0][nn] = v.x; ts[kg + 1][nn] = v.y; ts[kg + 2][nn] = v.z; ts[kg + 3][nn] = v.w;
        __syncthreads();
        float4 o = make_float4(ts[kk][n4], ts[kk][n4 + 1], ts[kk][n4 + 2], ts[kk][n4 + 3]);
        *(float4*)&g_xT[(((size_t)(b * KDIM + kk) * CC + c) * NNDIM) + n0 + n4] = o;
        __syncthreads();
    }
}

// ---------------- shared GEMM mainloop: C[128 x 64] tile, 256 thr, 8x4 micro ----------------
__device__ __forceinline__ void gemm_main(const float* __restrict__ Arow0, int lda,
                                          const float* __restrict__ B0, int ldb, int kdim,
                                          int t, float acc[8][4],
                                          float (*As)[128], float (*Bs)[64]) {
    int ar = t & 127, ak = (t >> 7) << 3;
    int bk = t >> 4,  bn = (t & 15) << 2;
    int tm = (t >> 4) << 3, tn = (t & 15) << 2;
    for (int k0 = 0; k0 < kdim; k0 += 16) {
        float4 a0 = *(const float4*)&Arow0[(size_t)ar * lda + k0 + ak];
        float4 a1 = *(const float4*)&Arow0[(size_t)ar * lda + k0 + ak + 4];
        float4 bb = *(const float4*)&B0[(size_t)(k0 + bk) * ldb + bn];
        __syncthreads();
        As[ak + 0][ar] = a0.x; As[ak + 1][ar] = a0.y; As[ak + 2][ar] = a0.z; As[ak + 3][ar] = a0.w;
        As[ak + 4][ar] = a1.x; As[ak + 5][ar] = a1.y; As[ak + 6][ar] = a1.z; As[ak + 7][ar] = a1.w;
        *(float4*)&Bs[bk][bn] = bb;
        __syncthreads();
#pragma unroll
        for (int kk = 0; kk < 16; kk++) {
            float4 x0 = *(float4*)&As[kk][tm];
            float4 x1 = *(float4*)&As[kk][tm + 4];
            float4 y  = *(float4*)&Bs[kk][tn];
            acc[0][0] += x0.x * y.x; acc[0][1] += x0.x * y.y; acc[0][2] += x0.x * y.z; acc[0][3] += x0.x * y.w;
            acc[1][0] += x0.y * y.x; acc[1][1] += x0.y * y.y; acc[1][2] += x0.y * y.z; acc[1][3] += x0.y * y.w;
            acc[2][0] += x0.z * y.x; acc[2][1] += x0.z * y.y; acc[2][2] += x0.z * y.z; acc[2][3] += x0.z * y.w;
            acc[3][0] += x0.w * y.x; acc[3][1] += x0.w * y.y; acc[3][2] += x0.w * y.z; acc[3][3] += x0.w * y.w;
            acc[4][0] += x1.x * y.x; acc[4][1] += x1.x * y.y; acc[4][2] += x1.x * y.z; acc[4][3] += x1.x * y.w;
            acc[5][0] += x1.y * y.x; acc[5][1] += x1.y * y.y; acc[5][2] += x1.y * y.z; acc[5][3] += x1.y * y.w;
            acc[6][0] += x1.z * y.x; acc[6][1] += x1.z * y.y; acc[6][2] += x1.z * y.z; acc[6][3] += x1.z * y.w;
            acc[7][0] += x1.w * y.x; acc[7][1] += x1.w * y.y; acc[7][2] += x1.w * y.z; acc[7][3] += x1.w * y.w;
        }
    }
}

// ---------------- kernel 2: fused q/k/v projection ----------------
// out[o, (b,k,n)] = Wcat[o,:] . xT[b,k,:,n]; grid (256 j-tiles, 3 m-tiles, 8 b)
__global__ void k_proj(const float* __restrict__ v_b) {
    __shared__ float As[16][128];
    __shared__ float Bs[16][64];
    int b = blockIdx.z;
    int jt = blockIdx.x;
    int kb = jt >> 4;
    int n0 = (jt & 15) << 6;
    int m0 = blockIdx.y << 7;
    int t = threadIdx.x;
    const float* Bbase = g_xT + ((size_t)(b * KDIM + kb) * CC) * NNDIM + n0;
    float acc[8][4] = {};
    gemm_main(g_wcat + (size_t)m0 * 256, 256, Bbase, NNDIM, 256, t, acc, As, Bs);
    int tm = (t >> 4) << 3, tn = (t & 15) << 2;
#pragma unroll
    for (int i = 0; i < 8; i++) {
        int o = m0 + tm + i;
        float4 r = make_float4(acc[i][0], acc[i][1], acc[i][2], acc[i][3]);
        if (o < 64) {
            *(float4*)&g_xq[((size_t)(b * KDIM + kb) * CQ + o) * NNDIM + n0 + tn] = r;
        } else if (o < 128) {
            *(float4*)&g_xk[((size_t)(b * KDIM + kb) * CQ + (o - 64)) * NNDIM + n0 + tn] = r;
        } else {
            float bias = v_b[o - 128];
            r.x += bias; r.y += bias; r.z += bias; r.w += bias;
            *(float4*)&g_xv[((size_t)(b * KDIM + kb) * CC + (o - 128)) * NNDIM + n0 + tn] = r;
        }
    }
}

// ---------------- kernel 3: energy + softmax ----------------
// per (b,k): E[n,m] = sum_d q[d,n]*k[d,m]; softmax rows; write S.
#define ES 1028
#define SMEM_E ((16 * ES + 64 * 128 + 64 * 16) * 4)
__global__ void k_energy() {
    extern __shared__ float sh[];
    float* e_s = sh;                    // [16][ES]
    float* k_s = sh + 16 * ES;          // [64][128]
    float* q_s = k_s + 64 * 128;        // [64][16]
    int z  = blockIdx.y;                // b*16 + k
    int n0 = blockIdx.x << 4;
    int t  = threadIdx.x;
    const float* qg = g_xq + (size_t)z * CQ * NNDIM;
    const float* kg = g_xk + (size_t)z * CQ * NNDIM;
    {   // load q block [64 cq][16 n]
        int cc = t >> 2, nn = (t & 3) << 2;
        float4 v = *(const float4*)&qg[(size_t)cc * NNDIM + n0 + nn];
        *(float4*)&q_s[cc * 16 + nn] = v;
    }
    __syncthreads();
    int r = t & 15, mg = t >> 4;
    for (int m0 = 0; m0 < NNDIM; m0 += 128) {
#pragma unroll
        for (int i = 0; i < 8; i++) {   // load k_s [64][128]
            int fl = t + i * 256;
            int cc = fl >> 5, m4 = (fl & 31) << 2;
            float4 v = *(const float4*)&kg[(size_t)cc * NNDIM + m0 + m4];
            *(float4*)&k_s[cc * 128 + m4] = v;
        }
        __syncthreads();
        float a[8] = {0, 0, 0, 0, 0, 0, 0, 0};
#pragma unroll
        for (int cc = 0; cc < 64; cc++) {
            float qv  = q_s[cc * 16 + r];
            float4 k0 = *(float4*)&k_s[cc * 128 + mg * 8];
            float4 k1 = *(float4*)&k_s[cc * 128 + mg * 8 + 4];
            a[0] += qv * k0.x; a[1] += qv * k0.y; a[2] += qv * k0.z; a[3] += qv * k0.w;
            a[4] += qv * k1.x; a[5] += qv * k1.y; a[6] += qv * k1.z; a[7] += qv * k1.w;
        }
        *(float4*)&e_s[r * ES + m0 + mg * 8]     = make_float4(a[0], a[1], a[2], a[3]);
        *(float4*)&e_s[r * ES + m0 + mg * 8 + 4] = make_float4(a[4], a[5], a[6], a[7]);
        __syncthreads();
    }
    // softmax: row rr handled by 16 threads (lr)
    int lr = t & 15, rr = t >> 4;
    const unsigned FULL = 0xffffffffu;
    float* row = e_s + rr * ES;
    float mx = -1e30f;
#pragma unroll
    for (int i = 0; i < 16; i++) {
        float4 v = *(float4*)&row[i * 64 + lr * 4];
        mx = fmaxf(mx, fmaxf(fmaxf(v.x, v.y), fmaxf(v.z, v.w)));
    }
    mx = fmaxf(mx, __shfl_xor_sync(FULL, mx, 1));
    mx = fmaxf(mx, __shfl_xor_sync(FULL, mx, 2));
    mx = fmaxf(mx, __shfl_xor_sync(FULL, mx, 4));
    mx = fmaxf(mx, __shfl_xor_sync(FULL, mx, 8));
    float sum = 0.0f;
#pragma unroll
    for (int i = 0; i < 16; i++) {
        float4 v = *(float4*)&row[i * 64 + lr * 4];
        v.x = __expf(v.x - mx); v.y = __expf(v.y - mx);
        v.z = __expf(v.z - mx); v.w = __expf(v.w - mx);
        sum += v.x + v.y + v.z + v.w;
        *(float4*)&row[i * 64 + lr * 4] = v;
    }
    sum += __shfl_xor_sync(FULL, sum, 1);
    sum += __shfl_xor_sync(FULL, sum, 2);
    sum += __shfl_xor_sync(FULL, sum, 4);
    sum += __shfl_xor_sync(FULL, sum, 8);
    float inv = 1.0f / sum;
    float* Srow = g_S + ((size_t)z * NNDIM + n0 + rr) * NNDIM;
#pragma unroll
    for (int i = 0; i < 16; i++) {
        int col = (i * 16 + lr) * 4;
        float4 v = *(float4*)&row[col];
        v.x *= inv; v.y *= inv; v.z *= inv; v.w *= inv;
        *(float4*)&Srow[col] = v;
    }
}

// ---------------- kernel 4: cross-K renormalization ----------------
__global__ void k_renorm() {
    size_t p = (size_t)blockIdx.x * 256 + threadIdx.x;   // < 8*1024*256
    int m = (int)(p & 255) << 2;
    int n = (int)(p >> 8) & 1023;
    int b = (int)(p >> 18);
    size_t base = (((size_t)b * KDIM) * NNDIM + n) * NNDIM + m;
    const size_t ks = (size_t)NNDIM * NNDIM;
    float4 v[16];
    float4 s = make_float4(1e-9f, 1e-9f, 1e-9f, 1e-9f);
#pragma unroll
    for (int k = 0; k < 16; k++) {
        v[k] = *(const float4*)&g_S[base + (size_t)k * ks];
        s.x += v[k].x; s.y += v[k].y; s.z += v[k].z; s.w += v[k].w;
    }
    float4 inv = make_float4(1.0f / s.x, 1.0f / s.y, 1.0f / s.z, 1.0f / s.w);
#pragma unroll
    for (int k = 0; k < 16; k++) {
        v[k].x *= inv.x; v[k].y *= inv.y; v[k].z *= inv.z; v[k].w *= inv.w;
        *(float4*)&g_S[base + (size_t)k * ks] = v[k];
    }
}

// ---------------- kernel 5: x_r = x_v @ A, d = xT - x_r ----------------
__global__ void k_xr() {
    __shared__ float As[16][128];
    __shared__ float Bs[16][64];
    int z  = blockIdx.z;            // b*16+k
    int m0 = blockIdx.y << 7;       // channel tile (0/128)
    int j0 = blockIdx.x << 6;       // output column tile
    int t  = threadIdx.x;
    const float* Ab = g_xv + (size_t)z * CC * NNDIM + (size_t)m0 * NNDIM;
    const float* Bb = g_S + (size_t)z * NNDIM * NNDIM + j0;
    float acc[8][4] = {};
    gemm_main(Ab, NNDIM, Bb, NNDIM, NNDIM, t, acc, As, Bs);
    int tm = (t >> 4) << 3, tn = (t & 15) << 2;
#pragma unroll
    for (int i = 0; i < 8; i++) {
        size_t idx = ((size_t)z * CC + m0 + tm + i) * NNDIM + j0 + tn;
        float4 xt = *(const float4*)&g_xT[idx];
        float4 r = make_float4(xt.x - acc[i][0], xt.y - acc[i][1],
                               xt.z - acc[i][2], xt.w - acc[i][3]);
        *(float4*)&g_d[idx] = r;
    }
}

// ---------------- kernel 6: t = t_w @ d + t_b -> [b][c][k][n] ----------------
__global__ void k_tproj(const float* __restrict__ t_w, const float* __restrict__ t_b) {
    __shared__ float As[16][128];
    __shared__ float Bs[16][64];
    int b  = blockIdx.z;
    int jt = blockIdx.x;
    int kb = jt >> 4;
    int n0 = (jt & 15) << 6;
    int m0 = blockIdx.y << 7;
    int t  = threadIdx.x;
    const float* Bbase = g_d + ((size_t)(b * KDIM + kb) * CC) * NNDIM + n0;
    float acc[8][4] = {};
    gemm_main(t_w + (size_t)m0 * 256, 256, Bbase, NNDIM, 256, t, acc, As, Bs);
    int tm = (t >> 4) << 3, tn = (t & 15) << 2;
#pragma unroll
    for (int i = 0; i < 8; i++) {
        int o = m0 + tm + i;
        float bias = t_b[o];
        float4 r = make_float4(acc[i][0] + bias, acc[i][1] + bias,
                               acc[i][2] + bias, acc[i][3] + bias);
        *(float4*)&g_t[(((size_t)(b * CC + o)) * KDIM + kb) * NNDIM + n0 + tn] = r;
    }
}

// ---------------- kernel 7: BN stats per channel ----------------
__global__ void k_stats(const float* __restrict__ gamma, const float* __restrict__ beta) {
    int c = blockIdx.x;
    int t = threadIdx.x;
    float s = 0.0f, sq = 0.0f;
    for (int b = 0; b < BB; b++) {
        const float* base = g_t + ((size_t)(b * CC + c)) * KDIM * NNDIM;
        for (int fl = t; fl < 4096; fl += 256) {
            float4 v = *(const float4*)&base[fl * 4];
            s  += v.x + v.y + v.z + v.w;
            sq += v.x * v.x + v.y * v.y + v.z * v.z + v.w * v.w;
        }
    }
    __shared__ float ss[256], sqq[256];
    ss[t] = s; sqq[t] = sq;
    __syncthreads();
    for (int o = 128; o > 0; o >>= 1) {
        if (t < o) { ss[t] += ss[t + o]; sqq[t] += sqq[t + o]; }
        __syncthreads();
    }
    if (t == 0) {
        const float cnt = 131072.0f;   // B*N*K
        float mean = ss[0] / cnt;
        float var  = sqq[0] / cnt - mean * mean;
        float rstd = rsqrtf(var + 1e-5f);
        float a = rstd * gamma[c];
        g_a[c]  = a;
        g_b2[c] = beta[c] - mean * a;
    }
}

// ---------------- kernel 8: out = x + relu(t*a + b2), transpose [k][n]->[n][k] ----------------
__global__ void k_final(const float* __restrict__ x, float* __restrict__ out) {
    __shared__ float ts[16][68];
    int bc = blockIdx.x;
    int c  = bc & 255;
    int t  = threadIdx.x;
    float a = g_a[c], b2 = g_b2[c];
    int kk = t >> 4, n4 = (t & 15) << 2;   // load mapping
    int nn = t >> 2, kg = (t & 3) << 2;    // store mapping
    for (int n0 = 0; n0 < NNDIM; n0 += 64) {
        float4 v = *(const float4*)&g_t[((size_t)bc * KDIM + kk) * NNDIM + n0 + n4];
        *(float4*)&ts[kk][n4] = v;
        __syncthreads();
        float4 tv = make_float4(ts[kg][nn], ts[kg + 1][nn], ts[kg + 2][nn], ts[kg + 3][nn]);
        tv.x = fmaxf(tv.x * a + b2, 0.0f);
        tv.y = fmaxf(tv.y * a + b2, 0.0f);
        tv.z = fmaxf(tv.z * a + b2, 0.0f);
        tv.w = fmaxf(tv.w * a + b2, 0.0f);
        size_t idx = ((size_t)bc * NNDIM + n0 + nn) * KDIM + kg;
        float4 xv = *(const float4*)&x[idx];
        tv.x += xv.x; tv.y += xv.y; tv.z += xv.z; tv.w += xv.w;
        *(float4*)&out[idx] = tv;
        __syncthreads();
    }
}

// ---------------- launch ----------------
extern "C" void kernel_launch(void* const* d_in, const int* in_sizes, int n_in,
                              void* d_out, int out_size) {
    const float* x     = (const float*)d_in[0];
    const float* q_w   = (const float*)d_in[1];
    const float* k_w   = (const float*)d_in[2];
    const float* v_w   = (const float*)d_in[3];
    const float* v_b   = (const float*)d_in[4];
    const float* t_w   = (const float*)d_in[5];
    const float* t_b   = (const float*)d_in[6];
    const float* gamma = (const float*)d_in[7];
    const float* beta  = (const float*)d_in[8];
    float* out = (float*)d_out;

    cudaFuncSetAttribute(k_energy, cudaFuncAttributeMaxDynamicSharedMemorySize, SMEM_E);

    k_concat<<<384, 256>>>(q_w, k_w, v_w);
    k_transpose_x<<<BB * CC, 256>>>(x);
    k_proj<<<dim3(256, 3, BB), 256>>>(v_b);
    k_energy<<<dim3(64, BB * KDIM), 256, SMEM_E>>>();
    k_renorm<<<8192, 256>>>();
    k_xr<<<dim3(16, 2, BB * KDIM), 256>>>();
    k_tproj<<<dim3(256, 2, BB), 256>>>(t_w, t_b);
    k_stats<<<CC, 256>>>(gamma, beta);
    k_final<<<BB * CC, 256>>>(x, out);
}

// round 3
// speedup vs baseline: 1.5478x; 1.5478x over previous
#include <cuda_runtime.h>
#include <cstdint>
#include <cstddef>

#define BB 8
#define CC 256
#define NNDIM 1024
#define KDIM 16
#define CQ 64

// ---------------- scratch (device globals; no allocation allowed) ----------------
__device__ float g_wcat[384 * 256];                         // concat q/k/v weights
__device__ float g_xT[(size_t)BB * KDIM * CC * NNDIM];      // [b][k][c][n]  134MB
__device__ float g_xq[(size_t)BB * KDIM * CQ * NNDIM];      // [b][k][cq][n]
__device__ float g_xk[(size_t)BB * KDIM * CQ * NNDIM];      // [b][k][cq][n]
__device__ float g_xv[(size_t)BB * KDIM * CC * NNDIM];      // [b][k][c][n]
__device__ float g_S [(size_t)BB * KDIM * NNDIM * NNDIM];   // S^T probs [z][m][n] 536MB
__device__ float g_d [(size_t)BB * KDIM * CC * NNDIM];      // x - x_r, [b][k][c][n]
__device__ float g_t [(size_t)BB * CC * KDIM * NNDIM];      // t proj, [b][c][k][n]
__device__ float g_a [CC];
__device__ float g_b2[CC];

__device__ __forceinline__ uint32_t f2tf32(float f) {
    uint32_t u;
    asm("cvt.rna.tf32.f32 %0, %1;" : "=r"(u) : "f"(f));
    return u;
}

__device__ __forceinline__ void mma_tf32(float c[4], const uint32_t a[4], const uint32_t b[2]) {
    asm volatile("mma.sync.aligned.m16n8k8.row.col.f32.tf32.tf32.f32 "
                 "{%0,%1,%2,%3}, {%4,%5,%6,%7}, {%8,%9}, {%0,%1,%2,%3};"
                 : "+f"(c[0]), "+f"(c[1]), "+f"(c[2]), "+f"(c[3])
                 : "r"(a[0]), "r"(a[1]), "r"(a[2]), "r"(a[3]), "r"(b[0]), "r"(b[1]));
}

// ---------------- kernel 0: concat weights ----------------
__global__ void k_concat(const float* __restrict__ q_w, const float* __restrict__ k_w,
                         const float* __restrict__ v_w) {
    int i = blockIdx.x * 256 + threadIdx.x;
    if (i >= 384 * 256) return;
    int o = i >> 8;
    float v;
    if (o < 64)        v = q_w[i];
    else if (o < 128)  v = k_w[i - 64 * 256];
    else               v = v_w[i - 128 * 256];
    g_wcat[i] = v;
}

// ---------------- kernel 1: transpose x [b,c,n,k] -> xT [b,k,c,n] ----------------
__global__ void k_transpose_x(const float* __restrict__ x) {
    __shared__ float ts[16][68];
    int bc = blockIdx.x;
    int b = bc >> 8, c = bc & 255;
    int t = threadIdx.x;
    int nn = t >> 2, kg = (t & 3) << 2;
    int kk = t >> 4, n4 = (t & 15) << 2;
    for (int n0 = 0; n0 < NNDIM; n0 += 64) {
        float4 v = *(const float4*)&x[(((size_t)bc * NNDIM) + n0 + nn) * KDIM + kg];
        ts[kg + 0][nn] = v.x; ts[kg + 1][nn] = v.y; ts[kg + 2][nn] = v.z; ts[kg + 3][nn] = v.w;
        __syncthreads();
        float4 o = make_float4(ts[kk][n4], ts[kk][n4 + 1], ts[kk][n4 + 2], ts[kk][n4 + 3]);
        *(float4*)&g_xT[(((size_t)(b * KDIM + kk) * CC + c) * NNDIM) + n0 + n4] = o;
        __syncthreads();
    }
}

// ---------------- unified tf32 mma.sync tile GEMM ----------------
// CTA: 128(M) x 128(N) output tile, 8 warps (2M x 4N), warp 64x32, K-chunk 32.
// A smem [m][k] (stride 36), B smem [n][k] (stride 36). Both operands K-major frags.
// MODE 0: xr   : A=g_xv[z],  B=g_S^T[z] (rows=N-dim, K-major). K=1024. epi: d = xT - acc
// MODE 1: proj : A=g_wcat,   B=g_xT[z]  (global [k][n], transpose-load). K=256. epi: split q/k/v
// MODE 2: tproj: A=t_w,      B=g_d[z]   (global [k][n], transpose-load). K=256. epi: +bias -> g_t
template<int MODE>
__global__ __launch_bounds__(256) void k_mma(const float* __restrict__ A_ext,
                                             const float* __restrict__ bias) {
    __shared__ uint32_t As[128][36];
    __shared__ uint32_t Bs[128][36];

    const int t = threadIdx.x;
    const int wid = t >> 5, lane = t & 31;
    const int gr = lane >> 2, tg = lane & 3;
    const int wm = (wid >> 2) * 64, wn = (wid & 3) * 32;
    const int z  = blockIdx.z;
    const int n0 = blockIdx.x << 7;
    const int m0 = blockIdx.y << 7;
    const int KTOT = (MODE == 0) ? 1024 : 256;
    const int NC = KTOT / 32;

    const float* Ap;
    const float* Bp;
    if (MODE == 0) {
        Ap = g_xv + ((size_t)z * CC + m0) * NNDIM;
        Bp = g_S + (size_t)z * NNDIM * NNDIM + (size_t)n0 * NNDIM;
    } else if (MODE == 1) {
        Ap = g_wcat + (size_t)m0 * 256;
        Bp = g_xT + (size_t)z * CC * NNDIM + n0;
    } else {
        Ap = A_ext + (size_t)m0 * 256;
        Bp = g_d + (size_t)z * CC * NNDIM + n0;
    }
    const int lda = (MODE == 0) ? NNDIM : 256;

    // staging registers
    float ra[16], rb[16];
    const int arow = t >> 1, ah = (t & 1) << 4;        // A: 2 thr/row, 16 floats each
    const int bc_ = t >> 3, bn4 = (t & 7) << 4;        // B transpose-load mapping

    auto loadA = [&](int k0) {
#pragma unroll
        for (int j = 0; j < 4; j++) {
            float4 v = *(const float4*)&Ap[(size_t)arow * lda + k0 + ah + j * 4];
            ra[j * 4 + 0] = v.x; ra[j * 4 + 1] = v.y; ra[j * 4 + 2] = v.z; ra[j * 4 + 3] = v.w;
        }
    };
    auto loadB = [&](int k0) {
        if (MODE == 0) {
#pragma unroll
            for (int j = 0; j < 4; j++) {
                float4 v = *(const float4*)&Bp[(size_t)arow * NNDIM + k0 + ah + j * 4];
                rb[j * 4 + 0] = v.x; rb[j * 4 + 1] = v.y; rb[j * 4 + 2] = v.z; rb[j * 4 + 3] = v.w;
            }
        } else {
#pragma unroll
            for (int j = 0; j < 4; j++) {
                float4 v = *(const float4*)&Bp[(size_t)(k0 + bc_) * NNDIM + bn4 + j * 4];
                rb[j * 4 + 0] = v.x; rb[j * 4 + 1] = v.y; rb[j * 4 + 2] = v.z; rb[j * 4 + 3] = v.w;
            }
        }
    };
    auto storeAB = [&]() {
#pragma unroll
        for (int j = 0; j < 16; j++) As[arow][ah + j] = f2tf32(ra[j]);
        if (MODE == 0) {
#pragma unroll
            for (int j = 0; j < 16; j++) Bs[arow][ah + j] = f2tf32(rb[j]);
        } else {
#pragma unroll
            for (int j = 0; j < 16; j++) Bs[bn4 + j][bc_] = f2tf32(rb[j]);
        }
    };

    float acc[4][4][4] = {};
    loadA(0); loadB(0);
    for (int c = 0; c < NC; c++) {
        __syncthreads();
        storeAB();
        __syncthreads();
        if (c + 1 < NC) { loadA((c + 1) * 32); loadB((c + 1) * 32); }
#pragma unroll
        for (int ks = 0; ks < 4; ks++) {
            int k0 = ks * 8;
            uint32_t af[4][4], bf[4][2];
#pragma unroll
            for (int mt = 0; mt < 4; mt++) {
                int r = wm + mt * 16 + gr;
                af[mt][0] = As[r][k0 + tg];
                af[mt][1] = As[r + 8][k0 + tg];
                af[mt][2] = As[r][k0 + tg + 4];
                af[mt][3] = As[r + 8][k0 + tg + 4];
            }
#pragma unroll
            for (int nt = 0; nt < 4; nt++) {
                int r = wn + nt * 8 + gr;
                bf[nt][0] = Bs[r][k0 + tg];
                bf[nt][1] = Bs[r][k0 + tg + 4];
            }
#pragma unroll
            for (int mt = 0; mt < 4; mt++)
#pragma unroll
                for (int nt = 0; nt < 4; nt++)
                    mma_tf32(acc[mt][nt], af[mt], bf[nt]);
        }
    }

    // ---------------- epilogue ----------------
#pragma unroll
    for (int mt = 0; mt < 4; mt++) {
#pragma unroll
        for (int nt = 0; nt < 4; nt++) {
#pragma unroll
            for (int h = 0; h < 2; h++) {       // row halves (gr, gr+8)
                int row = m0 + wm + mt * 16 + gr + h * 8;
                int col = n0 + wn + nt * 8 + 2 * tg;
                float v0 = acc[mt][nt][h * 2 + 0];
                float v1 = acc[mt][nt][h * 2 + 1];
                if (MODE == 0) {
                    size_t idx = ((size_t)z * CC + row) * NNDIM + col;
                    float2 xv = *(const float2*)&g_xT[idx];
                    float2 o = make_float2(xv.x - v0, xv.y - v1);
                    *(float2*)&g_d[idx] = o;
                } else if (MODE == 1) {
                    if (row < 64) {
                        *(float2*)&g_xq[((size_t)z * CQ + row) * NNDIM + col] = make_float2(v0, v1);
                    } else if (row < 128) {
                        *(float2*)&g_xk[((size_t)z * CQ + row - 64) * NNDIM + col] = make_float2(v0, v1);
                    } else {
                        float bb = bias[row - 128];
                        *(float2*)&g_xv[((size_t)z * CC + row - 128) * NNDIM + col] =
                            make_float2(v0 + bb, v1 + bb);
                    }
                } else {
                    float bb = bias[row];
                    int b = z >> 4, kb = z & 15;
                    *(float2*)&g_t[(((size_t)(b * CC + row)) * KDIM + kb) * NNDIM + col] =
                        make_float2(v0 + bb, v1 + bb);
                }
            }
        }
    }
}

// ---------------- kernel 3: energy + softmax (writes S^T [z][m][n]) ----------------
#define ES 1028
#define SMEM_E ((16 * ES + 64 * 128 + 64 * 16) * 4)
__global__ void k_energy() {
    extern __shared__ float sh[];
    float* e_s = sh;                    // [16][ES]
    float* k_s = sh + 16 * ES;          // [64][128]
    float* q_s = k_s + 64 * 128;        // [64][16] (reused for inv[16])
    int z  = blockIdx.y;
    int n0 = blockIdx.x << 4;
    int t  = threadIdx.x;
    const float* qg = g_xq + (size_t)z * CQ * NNDIM;
    const float* kg = g_xk + (size_t)z * CQ * NNDIM;
    {
        int cc = t >> 2, nn = (t & 3) << 2;
        float4 v = *(const float4*)&qg[(size_t)cc * NNDIM + n0 + nn];
        *(float4*)&q_s[cc * 16 + nn] = v;
    }
    __syncthreads();
    int r = t & 15, mg = t >> 4;
    for (int m0 = 0; m0 < NNDIM; m0 += 128) {
#pragma unroll
        for (int i = 0; i < 8; i++) {
            int fl = t + i * 256;
            int cc = fl >> 5, m4 = (fl & 31) << 2;
            float4 v = *(const float4*)&kg[(size_t)cc * NNDIM + m0 + m4];
            *(float4*)&k_s[cc * 128 + m4] = v;
        }
        __syncthreads();
        float a[8] = {0, 0, 0, 0, 0, 0, 0, 0};
#pragma unroll
        for (int cc = 0; cc < 64; cc++) {
            float qv  = q_s[cc * 16 + r];
            float4 k0 = *(float4*)&k_s[cc * 128 + mg * 8];
            float4 k1 = *(float4*)&k_s[cc * 128 + mg * 8 + 4];
            a[0] += qv * k0.x; a[1] += qv * k0.y; a[2] += qv * k0.z; a[3] += qv * k0.w;
            a[4] += qv * k1.x; a[5] += qv * k1.y; a[6] += qv * k1.z; a[7] += qv * k1.w;
        }
        *(float4*)&e_s[r * ES + m0 + mg * 8]     = make_float4(a[0], a[1], a[2], a[3]);
        *(float4*)&e_s[r * ES + m0 + mg * 8 + 4] = make_float4(a[4], a[5], a[6], a[7]);
        __syncthreads();
    }
    int lr = t & 15, rr = t >> 4;
    const unsigned FULL = 0xffffffffu;
    float* row = e_s + rr * ES;
    float mx = -1e30f;
#pragma unroll
    for (int i = 0; i < 16; i++) {
        float4 v = *(float4*)&row[i * 64 + lr * 4];
        mx = fmaxf(mx, fmaxf(fmaxf(v.x, v.y), fmaxf(v.z, v.w)));
    }
    mx = fmaxf(mx, __shfl_xor_sync(FULL, mx, 1));
    mx = fmaxf(mx, __shfl_xor_sync(FULL, mx, 2));
    mx = fmaxf(mx, __shfl_xor_sync(FULL, mx, 4));
    mx = fmaxf(mx, __shfl_xor_sync(FULL, mx, 8));
    float sum = 0.0f;
#pragma unroll
    for (int i = 0; i < 16; i++) {
        float4 v = *(float4*)&row[i * 64 + lr * 4];
        v.x = __expf(v.x - mx); v.y = __expf(v.y - mx);
        v.z = __expf(v.z - mx); v.w = __expf(v.w - mx);
        sum += v.x + v.y + v.z + v.w;
        *(float4*)&row[i * 64 + lr * 4] = v;
    }
    sum += __shfl_xor_sync(FULL, sum, 1);
    sum += __shfl_xor_sync(FULL, sum, 2);
    sum += __shfl_xor_sync(FULL, sum, 4);
    sum += __shfl_xor_sync(FULL, sum, 8);
    float* inv_s = q_s;
    if (lr == 0) inv_s[rr] = 1.0f / sum;
    __syncthreads();
    float* Sbase = g_S + (size_t)z * NNDIM * NNDIM;
#pragma unroll
    for (int pass = 0; pass < 4; pass++) {
        int m = pass * 256 + t;
        float* dst = Sbase + (size_t)m * NNDIM + n0;
#pragma unroll
        for (int g = 0; g < 4; g++) {
            float4 o;
            o.x = e_s[(g * 4 + 0) * ES + m] * inv_s[g * 4 + 0];
            o.y = e_s[(g * 4 + 1) * ES + m] * inv_s[g * 4 + 1];
            o.z = e_s[(g * 4 + 2) * ES + m] * inv_s[g * 4 + 2];
            o.w = e_s[(g * 4 + 3) * ES + m] * inv_s[g * 4 + 3];
            *(float4*)&dst[g * 4] = o;
        }
    }
}

// ---------------- kernel 4: cross-K renormalization (layout-agnostic) ----------------
__global__ void k_renorm() {
    size_t p = (size_t)blockIdx.x * 256 + threadIdx.x;
    int m = (int)(p & 255) << 2;
    int n = (int)(p >> 8) & 1023;
    int b = (int)(p >> 18);
    size_t base = (((size_t)b * KDIM) * NNDIM + n) * NNDIM + m;
    const size_t ks = (size_t)NNDIM * NNDIM;
    float4 v[16];
    float4 s = make_float4(1e-9f, 1e-9f, 1e-9f, 1e-9f);
#pragma unroll
    for (int k = 0; k < 16; k++) {
        v[k] = *(const float4*)&g_S[base + (size_t)k * ks];
        s.x += v[k].x; s.y += v[k].y; s.z += v[k].z; s.w += v[k].w;
    }
    float4 inv = make_float4(1.0f / s.x, 1.0f / s.y, 1.0f / s.z, 1.0f / s.w);
#pragma unroll
    for (int k = 0; k < 16; k++) {
        v[k].x *= inv.x; v[k].y *= inv.y; v[k].z *= inv.z; v[k].w *= inv.w;
        *(float4*)&g_S[base + (size_t)k * ks] = v[k];
    }
}

// ---------------- kernel 7: BN stats per channel ----------------
__global__ void k_stats(const float* __restrict__ gamma, const float* __restrict__ beta) {
    int c = blockIdx.x;
    int t = threadIdx.x;
    float s = 0.0f, sq = 0.0f;
    for (int b = 0; b < BB; b++) {
        const float* base = g_t + ((size_t)(b * CC + c)) * KDIM * NNDIM;
        for (int fl = t; fl < 4096; fl += 256) {
            float4 v = *(const float4*)&base[fl * 4];
            s  += v.x + v.y + v.z + v.w;
            sq += v.x * v.x + v.y * v.y + v.z * v.z + v.w * v.w;
        }
    }
    __shared__ float ss[256], sqq[256];
    ss[t] = s; sqq[t] = sq;
    __syncthreads();
    for (int o = 128; o > 0; o >>= 1) {
        if (t < o) { ss[t] += ss[t + o]; sqq[t] += sqq[t + o]; }
        __syncthreads();
    }
    if (t == 0) {
        const float cnt = 131072.0f;
        float mean = ss[0] / cnt;
        float var  = sqq[0] / cnt - mean * mean;
        float rstd = rsqrtf(var + 1e-5f);
        float a = rstd * gamma[c];
        g_a[c]  = a;
        g_b2[c] = beta[c] - mean * a;
    }
}

// ---------------- kernel 8: out = x + relu(t*a + b2), transpose [k][n]->[n][k] ----------------
__global__ void k_final(const float* __restrict__ x, float* __restrict__ out) {
    __shared__ float ts[16][68];
    int bc = blockIdx.x;
    int c  = bc & 255;
    int t  = threadIdx.x;
    float a = g_a[c], b2 = g_b2[c];
    int kk = t >> 4, n4 = (t & 15) << 2;
    int nn = t >> 2, kg = (t & 3) << 2;
    for (int n0 = 0; n0 < NNDIM; n0 += 64) {
        float4 v = *(const float4*)&g_t[((size_t)bc * KDIM + kk) * NNDIM + n0 + n4];
        *(float4*)&ts[kk][n4] = v;
        __syncthreads();
        float4 tv = make_float4(ts[kg][nn], ts[kg + 1][nn], ts[kg + 2][nn], ts[kg + 3][nn]);
        tv.x = fmaxf(tv.x * a + b2, 0.0f);
        tv.y = fmaxf(tv.y * a + b2, 0.0f);
        tv.z = fmaxf(tv.z * a + b2, 0.0f);
        tv.w = fmaxf(tv.w * a + b2, 0.0f);
        size_t idx = ((size_t)bc * NNDIM + n0 + nn) * KDIM + kg;
        float4 xv = *(const float4*)&x[idx];
        tv.x += xv.x; tv.y += xv.y; tv.z += xv.z; tv.w += xv.w;
        *(float4*)&out[idx] = tv;
        __syncthreads();
    }
}

// ---------------- launch ----------------
extern "C" void kernel_launch(void* const* d_in, const int* in_sizes, int n_in,
                              void* d_out, int out_size) {
    const float* x     = (const float*)d_in[0];
    const float* q_w   = (const float*)d_in[1];
    const float* k_w   = (const float*)d_in[2];
    const float* v_w   = (const float*)d_in[3];
    const float* v_b   = (const float*)d_in[4];
    const float* t_w   = (const float*)d_in[5];
    const float* t_b   = (const float*)d_in[6];
    const float* gamma = (const float*)d_in[7];
    const float* beta  = (const float*)d_in[8];
    float* out = (float*)d_out;

    cudaFuncSetAttribute(k_energy, cudaFuncAttributeMaxDynamicSharedMemorySize, SMEM_E);

    k_concat<<<384, 256>>>(q_w, k_w, v_w);
    k_transpose_x<<<BB * CC, 256>>>(x);
    k_mma<1><<<dim3(8, 3, BB * KDIM), 256>>>(nullptr, v_b);   // q/k/v projection
    k_energy<<<dim3(64, BB * KDIM), 256, SMEM_E>>>();
    k_renorm<<<8192, 256>>>();
    k_mma<0><<<dim3(8, 2, BB * KDIM), 256>>>(nullptr, nullptr); // x_r + (x - x_r)
    k_mma<2><<<dim3(8, 2, BB * KDIM), 256>>>(t_w, t_b);         // t projection
    k_stats<<<CC, 256>>>(gamma, beta);
    k_final<<<BB * CC, 256>>>(x, out);
}